// round 16
// baseline (speedup 1.0000x reference)
#include <cuda_runtime.h>
#include <cstdint>

#define MAPSZ 38809      // 197*197
#define NP    196        // 14*14 patches
#define HW    784        // 28*28
#define FULLM 0xFFFFFFFFu
#define SLOTP 7          // padded run slots per row (max runs in 14 bits = 7)
#define SL    98         // 14 * SLOTP

// scratch[z][(i*32 + b)*196 + p] = sum over 6 heads (z half) of att[i,b,j,0,1+p]
__device__ float        g_scratch[2][12 * 32 * NP];
// per-batch arrival counter; NEVER reset (epoch = mod 24), zero-init at load
__device__ unsigned int g_done[32];

// ---------------- Single fused kernel: 768 blocks ----------------
// Every block: phase-A partial for (layer i, batch b, head-half z).
// Last arriver per batch: warp 0 runs the full maskgen for that batch.
__global__ __launch_bounds__(224)
void fused_kernel(const float* __restrict__ att, float* __restrict__ out)
{
    __shared__ float    sh_a14[NP];     // 14x14 attention means
    __shared__ unsigned sh_data[SL];    // slot: runmask(16) | label<<16
    __shared__ int      sh_cnt[SL];     // per-root areas (14x14 cells)
    __shared__ unsigned sh_final[14];   // final 14x14 mask rows
    __shared__ unsigned sh_islast;

    const int i = blockIdx.x;      // layer 0..11
    const int b = blockIdx.y;      // batch 0..31
    const int z = blockIdx.z;      // head half 0..1
    const int p = threadIdx.x;     // patch 0..195

    // ---------- phase A partial: sum over 6 heads ----------
    if (p < NP) {
        const float* base = att + (size_t)(i * 384 + b * 12 + z * 6) * MAPSZ + 1 + p;
        float s0, s1, s2;
        s0 = __ldg(base + (size_t)0 * MAPSZ) + __ldg(base + (size_t)3 * MAPSZ);
        s1 = __ldg(base + (size_t)1 * MAPSZ) + __ldg(base + (size_t)4 * MAPSZ);
        s2 = __ldg(base + (size_t)2 * MAPSZ) + __ldg(base + (size_t)5 * MAPSZ);
        g_scratch[z][(i * 32 + b) * NP + p] = s0 + (s1 + s2);
    }
    __threadfence();               // publish scratch before signaling
    __syncthreads();
    if (threadIdx.x == 0) {
        const unsigned old = atomicAdd(&g_done[b], 1u);
        sh_islast = ((old % 24u) == 23u) ? 1u : 0u;   // epoch-safe across replays
    }
    __syncthreads();
    if (!sh_islast) return;
    if (threadIdx.x >= 32) return;                    // warp 0 carries on alone

    const int lane = threadIdx.x;
    __threadfence();               // acquire: all 24 producers' scratch visible

    // ---------- one-warp gather: a14[p] = (sum of 24 partials)/144 ----------
    float lanesum = 0.f;
    #pragma unroll
    for (int k = 0; k < 7; ++k) {
        const int pp = lane + 32 * k;
        if (pp < NP) {
            float s0 = 0.f, s1 = 0.f, s2 = 0.f, s3 = 0.f;
            #pragma unroll
            for (int l4 = 0; l4 < 12; l4 += 4) {
                s0 += g_scratch[0][((l4 + 0) * 32 + b) * NP + pp] + g_scratch[1][((l4 + 0) * 32 + b) * NP + pp];
                s1 += g_scratch[0][((l4 + 1) * 32 + b) * NP + pp] + g_scratch[1][((l4 + 1) * 32 + b) * NP + pp];
                s2 += g_scratch[0][((l4 + 2) * 32 + b) * NP + pp] + g_scratch[1][((l4 + 2) * 32 + b) * NP + pp];
                s3 += g_scratch[0][((l4 + 3) * 32 + b) * NP + pp] + g_scratch[1][((l4 + 3) * 32 + b) * NP + pp];
            }
            const float a = ((s0 + s1) + (s2 + s3)) / 144.0f;
            sh_a14[pp] = a;
            lanesum += a;
        }
    }
    // threshold = mean of a14 (== mean of the 28x28 upsample); butterfly allreduce
    float v = lanesum;
    #pragma unroll
    for (int off = 16; off > 0; off >>= 1)
        v += __shfl_xor_sync(FULLM, v, off);
    const float thr = v / 196.0f;
    __syncwarp();

    // ---------- mask rows (lane = row, 14 bits) ----------
    uint32_t m = 0;
    if (lane < 14) {
        #pragma unroll
        for (int x = 0; x < 14; ++x)
            m |= (sh_a14[lane * 14 + x] > thr) ? (1u << x) : 0u;
    }

    // ---------- run extraction into FIXED 7 slots/row; empty: mask=0, label=self ----------
    if (lane < 14) {
        uint32_t mm = m;
        #pragma unroll
        for (int j = 0; j < SLOTP; ++j) {
            uint32_t run = 0;
            if (mm) {
                const uint32_t lo = mm & (0u - mm);
                run = mm & ~(mm + lo);            // contiguous run containing lowest bit
                mm &= ~run;
            }
            const int s = lane * SLOTP + j;
            sh_data[s] = run | ((unsigned)s << 16);
            sh_cnt[s]  = 0;
        }
    }
    __syncwarp();

    // per-lane slot registers (up to 4 slots/lane)
    int      rr[4], rlab[4], rup[4], rdn[4];
    uint32_t rmk[4];
    bool     rv[4];
    #pragma unroll
    for (int k = 0; k < 4; ++k) {
        const int r = lane + 32 * k;
        rv[k]   = (r < SL);
        rr[k]   = rv[k] ? r : 0;
        const int row = rr[k] / SLOTP;
        rmk[k]  = rv[k] ? (sh_data[rr[k]] & 0xFFFFu) : 0u;
        rlab[k] = rr[k];
        rup[k]  = (row > 0)  ? (row - 1) * SLOTP : -1;
        rdn[k]  = (row < 13) ? (row + 1) * SLOTP : -1;
    }

    // ---------- min-label Jacobi + pointer jumping (warp-synchronous) ----------
    for (int it = 0; it < SL; ++it) {
        bool ch = false;
        #pragma unroll
        for (int k = 0; k < 4; ++k) {
            if (rv[k] && rmk[k]) {
                int vmin = rlab[k];
                const uint32_t mr = rmk[k];
                if (rup[k] >= 0) {
                    #pragma unroll
                    for (int j = 0; j < SLOTP; ++j) {
                        const unsigned d = sh_data[rup[k] + j];
                        if (d & mr) vmin = min(vmin, (int)(d >> 16));
                    }
                }
                if (rdn[k] >= 0) {
                    #pragma unroll
                    for (int j = 0; j < SLOTP; ++j) {
                        const unsigned d = sh_data[rdn[k] + j];
                        if (d & mr) vmin = min(vmin, (int)(d >> 16));
                    }
                }
                vmin = (int)(sh_data[vmin] >> 16);   // pointer jump
                vmin = (int)(sh_data[vmin] >> 16);
                if (vmin < rlab[k]) { rlab[k] = vmin; ch = true; }
            }
        }
        const unsigned any = __ballot_sync(FULLM, ch);
        __syncwarp();
        if (!any) break;
        #pragma unroll
        for (int k = 0; k < 4; ++k)
            if (rv[k]) sh_data[rr[k]] = rmk[k] | ((unsigned)rlab[k] << 16);
        __syncwarp();
    }

    // ---------- areas per root ----------
    #pragma unroll
    for (int k = 0; k < 4; ++k)
        if (rv[k] && rmk[k]) atomicAdd(&sh_cnt[rlab[k]], __popc(rmk[k]));
    __syncwarp();

    // best (area, min-cell): max area, tie -> smallest min cell (== argmax semantics).
    // Root = min slot of its component; slot order (row, j) is lex-monotone with
    // (row, leftmost x), so root's first bit IS the component's min flat cell.
    int bestkey = 0, bestroot = -1;
    #pragma unroll
    for (int k = 0; k < 4; ++k) {
        if (rv[k]) {
            const int c = sh_cnt[rr[k]];
            if (c > 0) {
                const int mc  = (rr[k] / SLOTP) * 14 + (__ffs(rmk[k]) - 1);
                const int key = (c << 8) | (255 - mc);     // unique per component
                if (key > bestkey) { bestkey = key; bestroot = rr[k]; }
            }
        }
    }
    const int gkey = __reduce_max_sync(FULLM, bestkey);
    const unsigned who = __ballot_sync(FULLM, (bestkey == gkey) && (gkey > 0));
    int groot = -1;
    if (who) groot = __shfl_sync(FULLM, bestroot, __ffs(who) - 1);

    const bool keep = (gkey > 0) && (((gkey >> 8) * 4) >= 160);  // THRESHOLD_POINT @28x28
    if (lane < 14) {
        uint32_t fin = m;
        if (keep) {
            fin = 0;
            #pragma unroll
            for (int j = 0; j < SLOTP; ++j) {
                const unsigned d = sh_data[lane * SLOTP + j];
                if ((d & 0xFFFFu) && ((int)(d >> 16) == groot)) fin |= (d & 0xFFFFu);
            }
        }
        sh_final[lane] = fin;
    }
    __syncwarp();

    // ---------- compaction: fg indices ascending, then bg ascending, +1 ----------
    const int myp = (lane < 14) ? __popc(sh_final[lane]) : 0;
    const int nfg = 4 * __reduce_add_sync(FULLM, myp);   // 28x28 fg count

    float* obase = out + b * HW;
    int fgrun = 0, bgrun = 0;
    #pragma unroll
    for (int c = 0; c < 25; ++c) {
        const int idx = c * 32 + lane;
        const bool valid = (idx < HW);
        int f = 0;
        if (valid) {
            const int y = idx / 28, x = idx - y * 28;
            f = (sh_final[y >> 1] >> (x >> 1)) & 1;
        }
        const unsigned balf = __ballot_sync(FULLM, f);
        const unsigned balv = __ballot_sync(FULLM, valid);
        const unsigned below = (1u << lane) - 1;
        const int prefg = __popc(balf & below);
        const int prev  = __popc(balv & below);
        if (valid) {
            const int pos = f ? (fgrun + prefg) : (nfg + bgrun + (prev - prefg));
            obase[pos] = (float)(idx + 1);   // __output__ is float32
        }
        fgrun += __popc(balf);
        bgrun += __popc(balv) - __popc(balf);
    }
}

extern "C" void kernel_launch(void* const* d_in, const int* in_sizes, int n_in,
                              void* d_out, int out_size)
{
    (void)in_sizes; (void)n_in; (void)out_size;
    const float* att = (const float*)d_in[0];
    float* out = (float*)d_out;

    dim3 grid(12, 32, 2);
    fused_kernel<<<grid, 224>>>(att, out);
}

// round 17
// speedup vs baseline: 2.3333x; 2.3333x over previous
#include <cuda_runtime.h>
#include <cstdint>

#define MAPSZ 38809      // 197*197
#define NP    196        // 14*14 patches
#define HW    784        // 28*28
#define FULLM 0xFFFFFFFFu

// scratch[z][(i*32 + b)*196 + p] = sum over 6 heads (z half) of att[i,b,j,0,1+p]
__device__ float g_scratch[2][12 * 32 * NP];

// ---------------- Kernel 1: wide phase-A reduction (768 blocks) ----------------
__global__ __launch_bounds__(224)
void phaseA_kernel(const float* __restrict__ att)
{
    const int i = blockIdx.x;      // layer 0..11
    const int b = blockIdx.y;      // batch 0..31
    const int z = blockIdx.z;      // head half 0..1
    const int p = threadIdx.x;     // patch 0..195
    if (p >= NP) return;

    const float* base = att + (size_t)(i * 384 + b * 12 + z * 6) * MAPSZ + 1 + p;
    float s0, s1, s2;
    s0 = __ldg(base + (size_t)0 * MAPSZ) + __ldg(base + (size_t)3 * MAPSZ);
    s1 = __ldg(base + (size_t)1 * MAPSZ) + __ldg(base + (size_t)4 * MAPSZ);
    s2 = __ldg(base + (size_t)2 * MAPSZ) + __ldg(base + (size_t)5 * MAPSZ);
    g_scratch[z][(i * 32 + b) * NP + p] = s0 + (s1 + s2);
}

// Kogge-Stone full-run horizontal fill: all bits of runs of m intersecting f.
__device__ __forceinline__ uint32_t fillH(uint32_t f, uint32_t m)
{
    uint32_t g = f, p = m;
    g |= p & (g << 1); p &= (p << 1);
    g |= p & (g << 2); p &= (p << 2);
    g |= p & (g << 4); p &= (p << 4);
    g |= p & (g << 8);
    uint32_t h = f, q = m;
    h |= q & (h >> 1); q &= (q >> 1);
    h |= q & (h >> 2); q &= (q >> 2);
    h |= q & (h >> 4); q &= (q >> 4);
    h |= q & (h >> 8);
    return (g | h) & m;
}

// ---------------- Kernel 2: threshold, deduped parallel bit-CCL, compaction ----------------
__global__ __launch_bounds__(1024, 1)
void maskgen_kernel(float* __restrict__ out)
{
    __shared__ float    sh_a14[NP];     // 14x14 attention means
    __shared__ float    sh_part[8];     // warp partial sums for threshold
    __shared__ unsigned sh_m[14];       // 14x14 mask rows
    __shared__ unsigned sh_rs[14];      // TOP-EDGE run-start bits per row
    __shared__ unsigned sh_final[14];   // final mask rows
    __shared__ int      sh_nruns, sh_key, sh_total;
    __shared__ int      sh_wsum[32], sh_wpre[32];

    const int b    = blockIdx.x;
    const int tid  = threadIdx.x;
    const int lane = tid & 31;
    const int w    = tid >> 5;

    // ---------- gather partial sums (L2-resident scratch) + per-warp reduce ----------
    float a = 0.f;
    if (tid < NP) {
        float s0 = 0.f, s1 = 0.f, s2 = 0.f, s3 = 0.f;
        #pragma unroll
        for (int i = 0; i < 12; i += 4) {
            s0 += g_scratch[0][((i + 0) * 32 + b) * NP + tid] + g_scratch[1][((i + 0) * 32 + b) * NP + tid];
            s1 += g_scratch[0][((i + 1) * 32 + b) * NP + tid] + g_scratch[1][((i + 1) * 32 + b) * NP + tid];
            s2 += g_scratch[0][((i + 2) * 32 + b) * NP + tid] + g_scratch[1][((i + 2) * 32 + b) * NP + tid];
            s3 += g_scratch[0][((i + 3) * 32 + b) * NP + tid] + g_scratch[1][((i + 3) * 32 + b) * NP + tid];
        }
        a = ((s0 + s1) + (s2 + s3)) / 144.0f;
        sh_a14[tid] = a;
    }
    if (w < 7) {                                 // tids 0..223 cover all 196 values
        float v = a;
        #pragma unroll
        for (int off = 16; off > 0; off >>= 1)
            v += __shfl_down_sync(FULLM, v, off);
        if (lane == 0) sh_part[w] = v;
    }
    if (tid == 0) sh_key = 0;
    __syncthreads();

    // ---------- warp 0: threshold, mask rows, TOP-EDGE run-starts ----------
    if (w == 0) {
        float v = (lane < 7) ? sh_part[lane] : 0.f;
        #pragma unroll
        for (int off = 16; off > 0; off >>= 1)
            v += __shfl_down_sync(FULLM, v, off);
        const float thr = __shfl_sync(FULLM, v, 0) / 196.0f;

        uint32_t m = 0;
        if (lane < 14) {
            #pragma unroll
            for (int x = 0; x < 14; ++x)
                m |= (sh_a14[lane * 14 + x] > thr) ? (1u << x) : 0u;
        }
        // mask of row above (lane-1); row 0 has nothing above
        uint32_t mu = __shfl_up_sync(FULLM, m, 1);
        if (lane == 0) mu = 0;

        // top-edge run-starts: lowest bit of each run with NO overlap above.
        // (A component's min cell is always in such a run.)
        uint32_t rs = 0;
        if (lane < 14) {
            uint32_t mm = m;
            #pragma unroll
            for (int j = 0; j < 7; ++j) {
                if (mm) {
                    const uint32_t lo  = mm & (0u - mm);
                    const uint32_t run = mm & ~(mm + lo);
                    if (!(run & mu)) rs |= lo;
                    mm &= ~run;
                }
            }
            sh_m[lane]  = m;
            sh_rs[lane] = rs;
        }
        const int nr = __reduce_add_sync(FULLM, (lane < 14) ? __popc(rs) : 0);
        if (lane == 0) sh_nruns = nr;
    }
    __syncthreads();

    // ---------- all warps: parallel flood-fill from deduped seeds ----------
    // 28x28 connectivity == 14x14 (2x nearest upsample); areas scale exactly 4x.
    const uint32_t mrow  = (lane < 14) ? sh_m[lane]  : 0u;
    const uint32_t rsrow = (lane < 14) ? sh_rs[lane] : 0u;
    const int nruns = sh_nruns;

    // exclusive prefix of seed counts per row (lane = row)
    int cnt = __popc(rsrow);
    int pre = cnt;
    #pragma unroll
    for (int off = 1; off < 32; off <<= 1) {
        int t = __shfl_up_sync(FULLM, pre, off);
        if (lane >= off) pre += t;
    }
    const int excl = pre - cnt;

    int      key_best = 0;
    uint32_t fbest    = 0;

    for (int k = w; k < nruns; k += 32) {
        unsigned sel = __ballot_sync(FULLM, (k >= excl) && (k < excl + cnt));
        int row = __ffs(sel) - 1;
        int j   = k - __shfl_sync(FULLM, excl, row);
        uint32_t bits = __shfl_sync(FULLM, rsrow, row);
        for (int t = 0; t < j; ++t) bits &= bits - 1;
        uint32_t f = (lane == row) ? (bits & (0u - bits)) : 0u;  // seed bit

        // flood: full horizontal runs + 1 vertical step per iteration
        while (true) {
            uint32_t fh = fillH(f, mrow);
            uint32_t up = __shfl_up_sync(FULLM, fh, 1);
            uint32_t dn = __shfl_down_sync(FULLM, fh, 1);
            if (lane == 0)  up = 0;
            if (lane == 31) dn = 0;
            uint32_t nf = fh | ((up | dn) & mrow);
            unsigned ch = __ballot_sync(FULLM, nf != f);
            f = nf;
            if (!ch) break;
        }

        int area = __reduce_add_sync(FULLM, __popc(f));
        unsigned nz = __ballot_sync(FULLM, f != 0);
        int r0 = __ffs(nz) - 1;
        uint32_t fr0 = __shfl_sync(FULLM, f, r0);
        int mincell = r0 * 14 + (__ffs(fr0) - 1);
        int key = (area << 8) | (255 - mincell);   // max area, tie -> min label
        if (key > key_best) { key_best = key; fbest = f; }
    }
    if (lane == 0 && key_best > 0) atomicMax(&sh_key, key_best);
    __syncthreads();

    const int gkey = sh_key;
    if (key_best == gkey && gkey > 0) {            // winner(s) write identical data
        const bool keep = ((gkey >> 8) * 4 >= 160);  // THRESHOLD_POINT at 28x28
        if (lane < 14) sh_final[lane] = keep ? fbest : mrow;
    }
    if (gkey == 0 && tid < 14) sh_final[tid] = 0;  // empty mask
    __syncthreads();

    // ---------- final 28x28 mask + stable "fg first, then bg" compaction ----------
    int f = 0;
    if (tid < HW) {
        int y = tid / 28, x = tid - y * 28;
        f = (sh_final[y >> 1] >> (x >> 1)) & 1;
    }
    unsigned bal = __ballot_sync(FULLM, f);
    const int lanepre = __popc(bal & ((1u << lane) - 1));
    if (lane == 0) sh_wsum[w] = __popc(bal);
    __syncthreads();
    if (w == 0) {
        int v = sh_wsum[lane];
        int inc = v;
        #pragma unroll
        for (int off = 1; off < 32; off <<= 1) {
            int t = __shfl_up_sync(FULLM, inc, off);
            if (lane >= off) inc += t;
        }
        sh_wpre[lane] = inc - v;
        if (lane == 31) sh_total = inc;   // total fg count
    }
    __syncthreads();

    if (tid < HW) {
        int fgpre = sh_wpre[w] + lanepre;
        int pos = f ? fgpre : (sh_total + (tid - fgpre));
        out[b * HW + pos] = (float)(tid + 1);   // __output__ is float32
    }
}

extern "C" void kernel_launch(void* const* d_in, const int* in_sizes, int n_in,
                              void* d_out, int out_size)
{
    (void)in_sizes; (void)n_in; (void)out_size;
    const float* att = (const float*)d_in[0];
    float* out = (float*)d_out;

    dim3 gridA(12, 32, 2);
    phaseA_kernel<<<gridA, 224>>>(att);
    maskgen_kernel<<<32, 1024>>>(out);
}